// round 11
// baseline (speedup 1.0000x reference)
#include <cuda_runtime.h>
#include <cstdint>

// BATCH=1024, L=2048, N_FEAT=11. Output: (1024,2048,8) bool -> float32 0/1.
#define BATCH_N 1024
#define LLEN    2048
#define NFEAT   11
#define NTHREADS 256

// Pattern table: 8 patterns x 8 floats.
// idx 0..3,7 = _TYPE_TABLE rows (rows 4..6 unreachable);
// idx 4 = MASK_NO_TIMESIGN, idx 5 = MASK_NO_TEMPO, idx 6 = MASK_FULL (== row3).
__constant__ float4 c_pat[8][2] = {
    { {0,1,0,0}, {0,0,0,0} },  // 0: TYPE_TABLE[0]
    { {0,1,1,0}, {0,0,0,0} },  // 1: TYPE_TABLE[1]
    { {0,0,0,0}, {1,0,0,0} },  // 2: TYPE_TABLE[2]
    { {0,0,0,1}, {1,1,1,1} },  // 3: TYPE_TABLE[3]
    { {0,0,0,0}, {0,1,0,0} },  // 4: NO_TIMESIGN
    { {0,0,0,0}, {0,0,1,0} },  // 5: NO_TEMPO
    { {0,0,0,1}, {1,1,1,1} },  // 6: FULL
    { {0,0,0,0}, {0,0,0,1} }   // 7: TYPE_TABLE[7]
};

__global__ __launch_bounds__(NTHREADS)
void mask_type_probs_kernel(const int* __restrict__ in,
                            float4* __restrict__ out)
{
    __shared__ int s_gt[LLEN];
    __shared__ int s_p5, s_p6;

    const int b   = blockIdx.x;
    const int tid = threadIdx.x;

    if (tid == 0) { s_p5 = LLEN; s_p6 = LLEN; }
    __syncthreads();

    const int* row = in + (size_t)b * LLEN * NFEAT;

    // Pass 1: load gt column (stride-11 int32) into shared; track local first
    // occurrence of 5 and 6.
    int lmin5 = LLEN, lmin6 = LLEN;
#pragma unroll
    for (int i = 0; i < LLEN / NTHREADS; i++) {
        const int t = tid + i * NTHREADS;
        const int g = __ldg(row + (size_t)t * NFEAT);
        s_gt[t] = g;
        if (g == 5 && t < lmin5) lmin5 = t;
        if (g == 6 && t < lmin6) lmin6 = t;
    }

#pragma unroll
    for (int o = 16; o > 0; o >>= 1) {
        lmin5 = min(lmin5, __shfl_down_sync(0xFFFFFFFFu, lmin5, o));
        lmin6 = min(lmin6, __shfl_down_sync(0xFFFFFFFFu, lmin6, o));
    }
    if ((tid & 31) == 0) {
        if (lmin5 < LLEN) atomicMin(&s_p5, lmin5);
        if (lmin6 < LLEN) atomicMin(&s_p6, lmin6);
    }
    __syncthreads();

    const int p5 = s_p5;  // first index with gt==5 (LLEN if none)
    const int p6 = s_p6;  // first index with gt==6 (LLEN if none)

    // Pass 2: per position emit 8 floats (two float4 stores, 32B coalesced).
    float4* orow = out + (size_t)b * LLEN * 2;
#pragma unroll
    for (int i = 0; i < LLEN / NTHREADS; i++) {
        const int t = tid + i * NTHREADS;
        const int g = s_gt[t];
        int m;
        if (g >= 4 && g <= 6) {
            const int ci = (t + 1 < LLEN - 1) ? (t + 1) : (LLEN - 1); // min(t+1, L-1)
            m = (ci < p5) ? 4 : ((ci < p6) ? 5 : 6);
        } else {
            m = g & 7;  // 0,1,2,3,7
        }
        orow[t * 2 + 0] = c_pat[m][0];
        orow[t * 2 + 1] = c_pat[m][1];
    }
}

extern "C" void kernel_launch(void* const* d_in, const int* in_sizes, int n_in,
                              void* d_out, int out_size)
{
    const int* in = (const int*)d_in[0];
    float4* out = (float4*)d_out;
    mask_type_probs_kernel<<<BATCH_N, NTHREADS>>>(in, out);
}

// round 12
// speedup vs baseline: 1.0060x; 1.0060x over previous
#include <cuda_runtime.h>
#include <cstdint>

// BATCH=1024, L=2048, N_FEAT=11. Output: (1024,2048,8) bool -> float32 0/1.
#define BATCH_N 1024
#define LLEN    2048
#define NFEAT   11
#define NTHREADS 256

// Pattern table: 8 patterns x 8 floats.
// idx 0..3,7 = _TYPE_TABLE rows (rows 4..6 unreachable);
// idx 4 = MASK_NO_TIMESIGN, idx 5 = MASK_NO_TEMPO, idx 6 = MASK_FULL (== row3).
__constant__ float4 c_pat[8][2] = {
    { {0,1,0,0}, {0,0,0,0} },  // 0: TYPE_TABLE[0]
    { {0,1,1,0}, {0,0,0,0} },  // 1: TYPE_TABLE[1]
    { {0,0,0,0}, {1,0,0,0} },  // 2: TYPE_TABLE[2]
    { {0,0,0,1}, {1,1,1,1} },  // 3: TYPE_TABLE[3]
    { {0,0,0,0}, {0,1,0,0} },  // 4: NO_TIMESIGN
    { {0,0,0,0}, {0,0,1,0} },  // 5: NO_TEMPO
    { {0,0,0,1}, {1,1,1,1} },  // 6: FULL
    { {0,0,0,0}, {0,0,0,1} }   // 7: TYPE_TABLE[7]
};

__global__ __launch_bounds__(NTHREADS)
void mask_type_probs_kernel(const int* __restrict__ in,
                            float4* __restrict__ out)
{
    __shared__ int s_gt[LLEN];
    __shared__ int s_p5, s_p6;

    const int b   = blockIdx.x;
    const int tid = threadIdx.x;

    if (tid == 0) { s_p5 = LLEN; s_p6 = LLEN; }
    __syncthreads();

    const int* row = in + (size_t)b * LLEN * NFEAT;

    // Pass 1: load gt column (stride-11 int32) into shared; track local first
    // occurrence of 5 and 6.
    int lmin5 = LLEN, lmin6 = LLEN;
#pragma unroll
    for (int i = 0; i < LLEN / NTHREADS; i++) {
        const int t = tid + i * NTHREADS;
        const int g = __ldg(row + (size_t)t * NFEAT);
        s_gt[t] = g;
        if (g == 5 && t < lmin5) lmin5 = t;
        if (g == 6 && t < lmin6) lmin6 = t;
    }

#pragma unroll
    for (int o = 16; o > 0; o >>= 1) {
        lmin5 = min(lmin5, __shfl_down_sync(0xFFFFFFFFu, lmin5, o));
        lmin6 = min(lmin6, __shfl_down_sync(0xFFFFFFFFu, lmin6, o));
    }
    if ((tid & 31) == 0) {
        if (lmin5 < LLEN) atomicMin(&s_p5, lmin5);
        if (lmin6 < LLEN) atomicMin(&s_p6, lmin6);
    }
    __syncthreads();

    const int p5 = s_p5;  // first index with gt==5 (LLEN if none)
    const int p6 = s_p6;  // first index with gt==6 (LLEN if none)

    // Pass 2: per position emit 8 floats (two float4 stores, 32B coalesced).
    float4* orow = out + (size_t)b * LLEN * 2;
#pragma unroll
    for (int i = 0; i < LLEN / NTHREADS; i++) {
        const int t = tid + i * NTHREADS;
        const int g = s_gt[t];
        int m;
        if (g >= 4 && g <= 6) {
            const int ci = (t + 1 < LLEN - 1) ? (t + 1) : (LLEN - 1); // min(t+1, L-1)
            m = (ci < p5) ? 4 : ((ci < p6) ? 5 : 6);
        } else {
            m = g & 7;  // 0,1,2,3,7
        }
        orow[t * 2 + 0] = c_pat[m][0];
        orow[t * 2 + 1] = c_pat[m][1];
    }
}

extern "C" void kernel_launch(void* const* d_in, const int* in_sizes, int n_in,
                              void* d_out, int out_size)
{
    const int* in = (const int*)d_in[0];
    float4* out = (float4*)d_out;
    mask_type_probs_kernel<<<BATCH_N, NTHREADS>>>(in, out);
}

// round 16
// speedup vs baseline: 1.1309x; 1.1242x over previous
#include <cuda_runtime.h>
#include <cstdint>

// BATCH=1024, L=2048, N_FEAT=11. Output: (1024,2048,8) bool -> float32 0/1.
#define BATCH_N 1024
#define LLEN    2048
#define NFEAT   11
#define NTHREADS 512
#define ITERS   (LLEN / NTHREADS)   // 4

// Pattern bytes, bit i = mask[i], byte m = pattern for selector m:
//  m0 TYPE_TABLE[0] = 0x02, m1 = 0x06, m2 = 0x10, m3 = 0xF8,
//  m4 NO_TIMESIGN   = 0x20, m5 NO_TEMPO = 0x40, m6 FULL = 0xF8,
//  m7 TYPE_TABLE[7] = 0x80
#define PAT_TAB 0x80F84020F8100602ULL

__global__ __launch_bounds__(NTHREADS)
void mask_type_probs_kernel(const int* __restrict__ in,
                            float4* __restrict__ out)
{
    __shared__ int s_p5, s_p6;

    const int b   = blockIdx.x;
    const int tid = threadIdx.x;

    if (tid == 0) { s_p5 = LLEN; s_p6 = LLEN; }

    const int* row = in + (size_t)b * LLEN * NFEAT;

    // Pass 1: load gt column (stride-11 int32) into REGISTERS; track local
    // first occurrence of 5 and 6. Loads are independent -> MLP=4/thread.
    int g[ITERS];
    int lmin5 = LLEN, lmin6 = LLEN;
#pragma unroll
    for (int i = 0; i < ITERS; i++) {
        const int t = tid + i * NTHREADS;
        g[i] = __ldcs(row + (size_t)t * NFEAT);
    }
#pragma unroll
    for (int i = 0; i < ITERS; i++) {
        const int t = tid + i * NTHREADS;
        if (g[i] == 5 && t < lmin5) lmin5 = t;
        if (g[i] == 6 && t < lmin6) lmin6 = t;
    }

    // Warp reduce first-occurrence indices, one atomicMin per warp.
#pragma unroll
    for (int o = 16; o > 0; o >>= 1) {
        lmin5 = min(lmin5, __shfl_down_sync(0xFFFFFFFFu, lmin5, o));
        lmin6 = min(lmin6, __shfl_down_sync(0xFFFFFFFFu, lmin6, o));
    }
    __syncthreads();   // covers the s_p5/s_p6 init too
    if ((tid & 31) == 0) {
        if (lmin5 < LLEN) atomicMin(&s_p5, lmin5);
        if (lmin6 < LLEN) atomicMin(&s_p6, lmin6);
    }
    __syncthreads();

    const int p5 = s_p5;  // first index with gt==5 (LLEN if none)
    const int p6 = s_p6;  // first index with gt==6 (LLEN if none)

    // Pass 2: per position emit 8 floats (two float4 streaming stores).
    // Pattern generated by pure ALU from a 64-bit byte table (no LDC replay).
    float4* orow = out + (size_t)b * LLEN * 2;
#pragma unroll
    for (int i = 0; i < ITERS; i++) {
        const int t  = tid + i * NTHREADS;
        const int gg = g[i];
        int m;
        if (gg >= 4 && gg <= 6) {
            const int ci = (t + 1 < LLEN - 1) ? (t + 1) : (LLEN - 1); // min(t+1,L-1)
            m = (ci < p5) ? 4 : ((ci < p6) ? 5 : 6);
        } else {
            m = gg;  // 0,1,2,3,7
        }
        const unsigned byte = (unsigned)(PAT_TAB >> (m * 8)) & 0xFFu;

        float4 lo, hi;
        lo.x = 0.0f;                             // bit 0 always 0
        lo.y = (byte & 0x02u) ? 1.0f : 0.0f;
        lo.z = (byte & 0x04u) ? 1.0f : 0.0f;
        lo.w = (byte & 0x08u) ? 1.0f : 0.0f;
        hi.x = (byte & 0x10u) ? 1.0f : 0.0f;
        hi.y = (byte & 0x20u) ? 1.0f : 0.0f;
        hi.z = (byte & 0x40u) ? 1.0f : 0.0f;
        hi.w = (byte & 0x80u) ? 1.0f : 0.0f;

        __stcs(&orow[(size_t)t * 2 + 0], lo);
        __stcs(&orow[(size_t)t * 2 + 1], hi);
    }
}

extern "C" void kernel_launch(void* const* d_in, const int* in_sizes, int n_in,
                              void* d_out, int out_size)
{
    const int* in = (const int*)d_in[0];
    float4* out = (float4*)d_out;
    mask_type_probs_kernel<<<BATCH_N, NTHREADS>>>(in, out);
}